// round 5
// baseline (speedup 1.0000x reference)
#include <cuda_runtime.h>
#include <cstddef>

#define B_   128
#define T_   1024
#define NI_  64
#define NH_  512
#define DT_C 0.01f

// Scratch (allocation-free rule: __device__ globals only)
__device__ float g_i2h[(size_t)B_ * T_ * NH_];   // 256 MB: tanh(x @ x2h), layout [B,T,NH]
__device__ float g_WT[NH_ * NH_];                // W^T so both GEMVs read coalesced

// ---------------------------------------------------------------------------
// Kernel 0: W^T  (g_WT[p][q] = W[q][p])
// ---------------------------------------------------------------------------
__global__ void k_transpose(const float* __restrict__ W) {
    __shared__ float tile[32][33];
    int x = blockIdx.x * 32 + threadIdx.x;
    int y = blockIdx.y * 32 + threadIdx.y;
    #pragma unroll
    for (int i = 0; i < 32; i += 8)
        tile[threadIdx.y + i][threadIdx.x] = W[(size_t)(y + i) * NH_ + x];
    __syncthreads();
    int x2 = blockIdx.y * 32 + threadIdx.x;
    int y2 = blockIdx.x * 32 + threadIdx.y;
    #pragma unroll
    for (int i = 0; i < 32; i += 8)
        g_WT[(size_t)(y2 + i) * NH_ + x2] = tile[threadIdx.x][threadIdx.y + i];
}

// ---------------------------------------------------------------------------
// Kernel 1: i2h = tanh(x @ x2h).  x: [B*T, 64] row-major, x2h: [64, 512].
// Tile 64(bt) x 64(h), K=64 whole. 256 threads, 4x4 micro-tile per thread.
// ---------------------------------------------------------------------------
__global__ __launch_bounds__(256) void k_i2h(const float* __restrict__ x,
                                             const float* __restrict__ x2h) {
    __shared__ float xsT[64][64];   // [k][m]
    __shared__ float ws[64][64];    // [k][n]
    int row0 = blockIdx.y * 64;
    int col0 = blockIdx.x * 64;
    int tid  = threadIdx.x;

    // x tile: rows [row0,row0+64) are a contiguous 4096-float block
    const float4* xsrc = reinterpret_cast<const float4*>(x + (size_t)row0 * NI_);
    for (int i = tid; i < 1024; i += 256) {
        float4 v = xsrc[i];
        int m = i >> 4;            // float index 4i: row = 4i/64
        int k = (i & 15) * 4;      // col-in-K
        xsT[k + 0][m] = v.x; xsT[k + 1][m] = v.y;
        xsT[k + 2][m] = v.z; xsT[k + 3][m] = v.w;
    }
    // x2h tile: 64 K-rows x 64 cols
    for (int i = tid; i < 1024; i += 256) {
        int k = i >> 4;
        int c = (i & 15) * 4;
        float4 v = *reinterpret_cast<const float4*>(x2h + (size_t)k * NH_ + col0 + c);
        *reinterpret_cast<float4*>(&ws[k][c]) = v;
    }
    __syncthreads();

    int tx = tid & 15, ty = tid >> 4;
    int m0 = ty * 4, n0 = tx * 4;
    float acc[4][4] = {};
    #pragma unroll 4
    for (int k = 0; k < 64; k++) {
        float4 a = *reinterpret_cast<float4*>(&xsT[k][m0]);
        float4 b = *reinterpret_cast<float4*>(&ws[k][n0]);
        float av[4] = {a.x, a.y, a.z, a.w};
        float bv[4] = {b.x, b.y, b.z, b.w};
        #pragma unroll
        for (int i = 0; i < 4; i++)
            #pragma unroll
            for (int j = 0; j < 4; j++)
                acc[i][j] = fmaf(av[i], bv[j], acc[i][j]);
    }
    #pragma unroll
    for (int i = 0; i < 4; i++) {
        float4 o;
        o.x = tanhf(acc[i][0]); o.y = tanhf(acc[i][1]);
        o.z = tanhf(acc[i][2]); o.w = tanhf(acc[i][3]);
        *reinterpret_cast<float4*>(&g_i2h[(size_t)(row0 + m0 + i) * NH_ + col0 + n0]) = o;
    }
}

// ---------------------------------------------------------------------------
// Kernel 2: the scan. One CTA per 2 batch rows (64 CTAs), 512 threads.
// Thread j owns hidden unit j of both rows. hy/z in smem (shared across
// threads), hz in registers. No inter-CTA sync needed ever.
// Per step:  z = tanh(hy @ W + b);  rec = z @ W^T (via g_WT, coalesced);
//            hz += DT*(i2h - rec - hy - hz);  hy += DT*hz;  states[t] = hy.
// ---------------------------------------------------------------------------
__global__ __launch_bounds__(512) void k_scan(const float* __restrict__ W,
                                              const float* __restrict__ bias,
                                              float* __restrict__ out,
                                              int write_final) {
    __shared__ float hys[2][NH_];
    __shared__ float zs[2][NH_];

    const int j  = threadIdx.x;
    const int r0 = blockIdx.x * 2;
    const int r1 = r0 + 1;

    const float bj = bias[j];
    float hy0 = 0.f, hy1 = 0.f, hz0 = 0.f, hz1 = 0.f;
    hys[0][j] = 0.f; hys[1][j] = 0.f;
    __syncthreads();

    const float* __restrict__ i2h0p = g_i2h + (size_t)r0 * T_ * NH_ + j;
    const float* __restrict__ i2h1p = g_i2h + (size_t)r1 * T_ * NH_ + j;
    float* __restrict__ out0 = out + (size_t)r0 * T_ * NH_ + j;
    float* __restrict__ out1 = out + (size_t)r1 * T_ * NH_ + j;
    const float* __restrict__ wp  = W + j;      // W[i][j] at wp[i*NH]
    const float* __restrict__ wtp = g_WT + j;   // W^T[i][j] at wtp[i*NH]

    for (int t = 0; t < T_; t++) {
        // ---- phase 1: z = tanh(hy @ W + b) ----
        float a0 = 0.f, a1 = 0.f;
        #pragma unroll 2
        for (int i = 0; i < NH_; i += 4) {
            float w0 = wp[(size_t)(i + 0) * NH_];
            float w1 = wp[(size_t)(i + 1) * NH_];
            float w2 = wp[(size_t)(i + 2) * NH_];
            float w3 = wp[(size_t)(i + 3) * NH_];
            float4 h0 = *reinterpret_cast<const float4*>(&hys[0][i]);
            float4 h1 = *reinterpret_cast<const float4*>(&hys[1][i]);
            a0 = fmaf(h0.x, w0, a0); a0 = fmaf(h0.y, w1, a0);
            a0 = fmaf(h0.z, w2, a0); a0 = fmaf(h0.w, w3, a0);
            a1 = fmaf(h1.x, w0, a1); a1 = fmaf(h1.y, w1, a1);
            a1 = fmaf(h1.z, w2, a1); a1 = fmaf(h1.w, w3, a1);
        }
        zs[0][j] = tanhf(a0 + bj);
        zs[1][j] = tanhf(a1 + bj);
        __syncthreads();

        // ---- phase 2: rec = z @ W^T  (row j of W dotted with z) ----
        float rr0 = 0.f, rr1 = 0.f;
        #pragma unroll 2
        for (int i = 0; i < NH_; i += 4) {
            float w0 = wtp[(size_t)(i + 0) * NH_];
            float w1 = wtp[(size_t)(i + 1) * NH_];
            float w2 = wtp[(size_t)(i + 2) * NH_];
            float w3 = wtp[(size_t)(i + 3) * NH_];
            float4 q0 = *reinterpret_cast<const float4*>(&zs[0][i]);
            float4 q1 = *reinterpret_cast<const float4*>(&zs[1][i]);
            rr0 = fmaf(q0.x, w0, rr0); rr0 = fmaf(q0.y, w1, rr0);
            rr0 = fmaf(q0.z, w2, rr0); rr0 = fmaf(q0.w, w3, rr0);
            rr1 = fmaf(q1.x, w0, rr1); rr1 = fmaf(q1.y, w1, rr1);
            rr1 = fmaf(q1.z, w2, rr1); rr1 = fmaf(q1.w, w3, rr1);
        }

        // ---- state update (GAMMA = EPSILON = 1) ----
        float i0 = i2h0p[(size_t)t * NH_];
        float i1 = i2h1p[(size_t)t * NH_];
        hz0 += DT_C * (i0 - rr0 - hy0 - hz0);
        hy0 += DT_C * hz0;
        hz1 += DT_C * (i1 - rr1 - hy1 - hz1);
        hy1 += DT_C * hz1;

        hys[0][j] = hy0;
        hys[1][j] = hy1;
        out0[(size_t)t * NH_] = hy0;
        out1[(size_t)t * NH_] = hy1;
        __syncthreads();
    }

    if (write_final) {  // hy_f appended after all_states
        float* fin = out + (size_t)B_ * T_ * NH_;
        fin[(size_t)r0 * NH_ + j] = hy0;
        fin[(size_t)r1 * NH_ + j] = hy1;
    }
}

// ---------------------------------------------------------------------------
// Launch. Inputs (metadata order): x [128,1024,64] f32, x2h [64,512] f32,
// h2h [512,512] f32, bias [512] f32. Output f32: all_states [128,1024,512]
// then hy_f [128,512] (guarded by out_size).
// ---------------------------------------------------------------------------
extern "C" void kernel_launch(void* const* d_in, const int* in_sizes, int n_in,
                              void* d_out, int out_size) {
    const float* x    = (const float*)d_in[0];
    const float* x2h  = (const float*)d_in[1];
    const float* h2h  = (const float*)d_in[2];
    const float* bias = (const float*)d_in[3];
    float* out = (float*)d_out;

    const long long states_elems = (long long)B_ * T_ * NH_;
    int write_final = ((long long)out_size >= states_elems + (long long)B_ * NH_) ? 1 : 0;

    k_transpose<<<dim3(NH_ / 32, NH_ / 32), dim3(32, 8)>>>(h2h);
    k_i2h<<<dim3(NH_ / 64, (B_ * T_) / 64), 256>>>(x, x2h);
    k_scan<<<B_ / 2, NH_>>>(h2h, bias, out, write_final);
}

// round 6
// speedup vs baseline: 1.0073x; 1.0073x over previous
#include <cuda_runtime.h>
#include <cstddef>

#define B_   128
#define T_   1024
#define NI_  64
#define NH_  512
#define DT_C 0.01f

// Scratch (allocation-free rule: __device__ globals only)
__device__ float g_i2h[(size_t)B_ * T_ * NH_];   // 256 MB: tanh(x @ x2h), layout [B,T,NH]
__device__ float g_WT[NH_ * NH_];                // W^T so both GEMVs read coalesced

// ---------------------------------------------------------------------------
// Kernel 0: W^T  (g_WT[p][q] = W[q][p])
// ---------------------------------------------------------------------------
__global__ void k_transpose(const float* __restrict__ W) {
    __shared__ float tile[32][33];
    int x = blockIdx.x * 32 + threadIdx.x;
    int y = blockIdx.y * 32 + threadIdx.y;
    #pragma unroll
    for (int i = 0; i < 32; i += 8)
        tile[threadIdx.y + i][threadIdx.x] = W[(size_t)(y + i) * NH_ + x];
    __syncthreads();
    int x2 = blockIdx.y * 32 + threadIdx.x;
    int y2 = blockIdx.x * 32 + threadIdx.y;
    #pragma unroll
    for (int i = 0; i < 32; i += 8)
        g_WT[(size_t)(y2 + i) * NH_ + x2] = tile[threadIdx.x][threadIdx.y + i];
}

// ---------------------------------------------------------------------------
// Kernel 1: i2h = tanh(x @ x2h).  x: [B*T, 64] row-major, x2h: [64, 512].
// Tile 64(bt) x 64(h), K=64 whole. 256 threads, 4x4 micro-tile per thread.
// ---------------------------------------------------------------------------
__global__ __launch_bounds__(256) void k_i2h(const float* __restrict__ x,
                                             const float* __restrict__ x2h) {
    __shared__ float xsT[64][64];   // [k][m]
    __shared__ float ws[64][64];    // [k][n]
    int row0 = blockIdx.y * 64;
    int col0 = blockIdx.x * 64;
    int tid  = threadIdx.x;

    // x tile: rows [row0,row0+64) are a contiguous 4096-float block
    const float4* xsrc = reinterpret_cast<const float4*>(x + (size_t)row0 * NI_);
    for (int i = tid; i < 1024; i += 256) {
        float4 v = xsrc[i];
        int m = i >> 4;            // float index 4i: row = 4i/64
        int k = (i & 15) * 4;      // col-in-K
        xsT[k + 0][m] = v.x; xsT[k + 1][m] = v.y;
        xsT[k + 2][m] = v.z; xsT[k + 3][m] = v.w;
    }
    // x2h tile: 64 K-rows x 64 cols
    for (int i = tid; i < 1024; i += 256) {
        int k = i >> 4;
        int c = (i & 15) * 4;
        float4 v = *reinterpret_cast<const float4*>(x2h + (size_t)k * NH_ + col0 + c);
        *reinterpret_cast<float4*>(&ws[k][c]) = v;
    }
    __syncthreads();

    int tx = tid & 15, ty = tid >> 4;
    int m0 = ty * 4, n0 = tx * 4;
    float acc[4][4] = {};
    #pragma unroll 4
    for (int k = 0; k < 64; k++) {
        float4 a = *reinterpret_cast<float4*>(&xsT[k][m0]);
        float4 b = *reinterpret_cast<float4*>(&ws[k][n0]);
        float av[4] = {a.x, a.y, a.z, a.w};
        float bv[4] = {b.x, b.y, b.z, b.w};
        #pragma unroll
        for (int i = 0; i < 4; i++)
            #pragma unroll
            for (int j = 0; j < 4; j++)
                acc[i][j] = fmaf(av[i], bv[j], acc[i][j]);
    }
    #pragma unroll
    for (int i = 0; i < 4; i++) {
        float4 o;
        o.x = tanhf(acc[i][0]); o.y = tanhf(acc[i][1]);
        o.z = tanhf(acc[i][2]); o.w = tanhf(acc[i][3]);
        *reinterpret_cast<float4*>(&g_i2h[(size_t)(row0 + m0 + i) * NH_ + col0 + n0]) = o;
    }
}

// ---------------------------------------------------------------------------
// Kernel 2: the scan. One CTA per 2 batch rows (64 CTAs), 512 threads.
// Thread j owns hidden unit j of both rows. hy/z in smem (shared across
// threads), hz in registers. No inter-CTA sync needed ever.
// Per step:  z = tanh(hy @ W + b);  rec = z @ W^T (via g_WT, coalesced);
//            hz += DT*(i2h - rec - hy - hz);  hy += DT*hz;  states[t] = hy.
// ---------------------------------------------------------------------------
__global__ __launch_bounds__(512) void k_scan(const float* __restrict__ W,
                                              const float* __restrict__ bias,
                                              float* __restrict__ out,
                                              int write_final) {
    __shared__ float hys[2][NH_];
    __shared__ float zs[2][NH_];

    const int j  = threadIdx.x;
    const int r0 = blockIdx.x * 2;
    const int r1 = r0 + 1;

    const float bj = bias[j];
    float hy0 = 0.f, hy1 = 0.f, hz0 = 0.f, hz1 = 0.f;
    hys[0][j] = 0.f; hys[1][j] = 0.f;
    __syncthreads();

    const float* __restrict__ i2h0p = g_i2h + (size_t)r0 * T_ * NH_ + j;
    const float* __restrict__ i2h1p = g_i2h + (size_t)r1 * T_ * NH_ + j;
    float* __restrict__ out0 = out + (size_t)r0 * T_ * NH_ + j;
    float* __restrict__ out1 = out + (size_t)r1 * T_ * NH_ + j;
    const float* __restrict__ wp  = W + j;      // W[i][j] at wp[i*NH]
    const float* __restrict__ wtp = g_WT + j;   // W^T[i][j] at wtp[i*NH]

    for (int t = 0; t < T_; t++) {
        // ---- phase 1: z = tanh(hy @ W + b) ----
        float a0 = 0.f, a1 = 0.f;
        #pragma unroll 2
        for (int i = 0; i < NH_; i += 4) {
            float w0 = wp[(size_t)(i + 0) * NH_];
            float w1 = wp[(size_t)(i + 1) * NH_];
            float w2 = wp[(size_t)(i + 2) * NH_];
            float w3 = wp[(size_t)(i + 3) * NH_];
            float4 h0 = *reinterpret_cast<const float4*>(&hys[0][i]);
            float4 h1 = *reinterpret_cast<const float4*>(&hys[1][i]);
            a0 = fmaf(h0.x, w0, a0); a0 = fmaf(h0.y, w1, a0);
            a0 = fmaf(h0.z, w2, a0); a0 = fmaf(h0.w, w3, a0);
            a1 = fmaf(h1.x, w0, a1); a1 = fmaf(h1.y, w1, a1);
            a1 = fmaf(h1.z, w2, a1); a1 = fmaf(h1.w, w3, a1);
        }
        zs[0][j] = tanhf(a0 + bj);
        zs[1][j] = tanhf(a1 + bj);
        __syncthreads();

        // ---- phase 2: rec = z @ W^T  (row j of W dotted with z) ----
        float rr0 = 0.f, rr1 = 0.f;
        #pragma unroll 2
        for (int i = 0; i < NH_; i += 4) {
            float w0 = wtp[(size_t)(i + 0) * NH_];
            float w1 = wtp[(size_t)(i + 1) * NH_];
            float w2 = wtp[(size_t)(i + 2) * NH_];
            float w3 = wtp[(size_t)(i + 3) * NH_];
            float4 q0 = *reinterpret_cast<const float4*>(&zs[0][i]);
            float4 q1 = *reinterpret_cast<const float4*>(&zs[1][i]);
            rr0 = fmaf(q0.x, w0, rr0); rr0 = fmaf(q0.y, w1, rr0);
            rr0 = fmaf(q0.z, w2, rr0); rr0 = fmaf(q0.w, w3, rr0);
            rr1 = fmaf(q1.x, w0, rr1); rr1 = fmaf(q1.y, w1, rr1);
            rr1 = fmaf(q1.z, w2, rr1); rr1 = fmaf(q1.w, w3, rr1);
        }

        // ---- state update (GAMMA = EPSILON = 1) ----
        float i0 = i2h0p[(size_t)t * NH_];
        float i1 = i2h1p[(size_t)t * NH_];
        hz0 += DT_C * (i0 - rr0 - hy0 - hz0);
        hy0 += DT_C * hz0;
        hz1 += DT_C * (i1 - rr1 - hy1 - hz1);
        hy1 += DT_C * hz1;

        hys[0][j] = hy0;
        hys[1][j] = hy1;
        out0[(size_t)t * NH_] = hy0;
        out1[(size_t)t * NH_] = hy1;
        __syncthreads();
    }

    if (write_final) {  // hy_f appended after all_states
        float* fin = out + (size_t)B_ * T_ * NH_;
        fin[(size_t)r0 * NH_ + j] = hy0;
        fin[(size_t)r1 * NH_ + j] = hy1;
    }
}

// ---------------------------------------------------------------------------
// Launch. Inputs (metadata order): x [128,1024,64] f32, x2h [64,512] f32,
// h2h [512,512] f32, bias [512] f32. Output f32: all_states [128,1024,512]
// then hy_f [128,512] (guarded by out_size).
// ---------------------------------------------------------------------------
extern "C" void kernel_launch(void* const* d_in, const int* in_sizes, int n_in,
                              void* d_out, int out_size) {
    const float* x    = (const float*)d_in[0];
    const float* x2h  = (const float*)d_in[1];
    const float* h2h  = (const float*)d_in[2];
    const float* bias = (const float*)d_in[3];
    float* out = (float*)d_out;

    const long long states_elems = (long long)B_ * T_ * NH_;
    int write_final = ((long long)out_size >= states_elems + (long long)B_ * NH_) ? 1 : 0;

    k_transpose<<<dim3(NH_ / 32, NH_ / 32), dim3(32, 8)>>>(h2h);
    k_i2h<<<dim3(NH_ / 64, (B_ * T_) / 64), 256>>>(x, x2h);
    k_scan<<<B_ / 2, NH_>>>(h2h, bias, out, write_final);
}

// round 7
// speedup vs baseline: 2.2290x; 2.2129x over previous
#include <cuda_runtime.h>
#include <cstddef>

#define B_   128
#define T_   1024
#define NI_  64
#define NH_  512
#define DT_C 0.01f

// Scratch (allocation-free rule: __device__ globals only)
__device__ float g_i2h[(size_t)B_ * T_ * NH_];   // 256 MB: tanh(x @ x2h), [B,T,NH]
__device__ float g_WT[NH_ * NH_];                // W^T for coalesced phase-2

// ---------------------------------------------------------------------------
// Kernel 0: W^T
// ---------------------------------------------------------------------------
__global__ void k_transpose(const float* __restrict__ W) {
    __shared__ float tile[32][33];
    int x = blockIdx.x * 32 + threadIdx.x;
    int y = blockIdx.y * 32 + threadIdx.y;
    #pragma unroll
    for (int i = 0; i < 32; i += 8)
        tile[threadIdx.y + i][threadIdx.x] = W[(size_t)(y + i) * NH_ + x];
    __syncthreads();
    int x2 = blockIdx.y * 32 + threadIdx.x;
    int y2 = blockIdx.x * 32 + threadIdx.y;
    #pragma unroll
    for (int i = 0; i < 32; i += 8)
        g_WT[(size_t)(y2 + i) * NH_ + x2] = tile[threadIdx.x][threadIdx.y + i];
}

// ---------------------------------------------------------------------------
// Kernel 1: i2h = tanh(x @ x2h).  x: [B*T, 64], x2h: [64, 512].
// ---------------------------------------------------------------------------
__global__ __launch_bounds__(256) void k_i2h(const float* __restrict__ x,
                                             const float* __restrict__ x2h) {
    __shared__ float xsT[64][64];   // [k][m]
    __shared__ float ws[64][64];    // [k][n]
    int row0 = blockIdx.y * 64;
    int col0 = blockIdx.x * 64;
    int tid  = threadIdx.x;

    const float4* xsrc = reinterpret_cast<const float4*>(x + (size_t)row0 * NI_);
    for (int i = tid; i < 1024; i += 256) {
        float4 v = xsrc[i];
        int m = i >> 4;
        int k = (i & 15) * 4;
        xsT[k + 0][m] = v.x; xsT[k + 1][m] = v.y;
        xsT[k + 2][m] = v.z; xsT[k + 3][m] = v.w;
    }
    for (int i = tid; i < 1024; i += 256) {
        int k = i >> 4;
        int c = (i & 15) * 4;
        float4 v = *reinterpret_cast<const float4*>(x2h + (size_t)k * NH_ + col0 + c);
        *reinterpret_cast<float4*>(&ws[k][c]) = v;
    }
    __syncthreads();

    int tx = tid & 15, ty = tid >> 4;
    int m0 = ty * 4, n0 = tx * 4;
    float acc[4][4] = {};
    #pragma unroll 4
    for (int k = 0; k < 64; k++) {
        float4 a = *reinterpret_cast<float4*>(&xsT[k][m0]);
        float4 b = *reinterpret_cast<float4*>(&ws[k][n0]);
        float av[4] = {a.x, a.y, a.z, a.w};
        float bv[4] = {b.x, b.y, b.z, b.w};
        #pragma unroll
        for (int i = 0; i < 4; i++)
            #pragma unroll
            for (int j = 0; j < 4; j++)
                acc[i][j] = fmaf(av[i], bv[j], acc[i][j]);
    }
    #pragma unroll
    for (int i = 0; i < 4; i++) {
        float4 o;
        o.x = tanhf(acc[i][0]); o.y = tanhf(acc[i][1]);
        o.z = tanhf(acc[i][2]); o.w = tanhf(acc[i][3]);
        *reinterpret_cast<float4*>(&g_i2h[(size_t)(row0 + m0 + i) * NH_ + col0 + n0]) = o;
    }
}

// ---------------------------------------------------------------------------
// Kernel 2: the scan. 64 CTAs x 512 threads, 2 batch rows per CTA.
// Thread layout for GEMV phases: cg = tid&127 -> 4 consecutive output cols,
// kq = tid>>7 -> K-quarter [kq*128, kq*128+128). Weights loaded as float4
// (coalesced LDG.128), hy/z as float2 smem broadcasts, 4-way partial
// reduction through smem. Thread tid owns state column tid of both rows.
// ---------------------------------------------------------------------------
__global__ __launch_bounds__(512) void k_scan(const float* __restrict__ W,
                                              const float* __restrict__ bias,
                                              float* __restrict__ out,
                                              int write_final) {
    __shared__ float2 hys[NH_];        // {row0, row1}
    __shared__ float2 zs[NH_];
    __shared__ float  part0[4][NH_];   // partials, row0
    __shared__ float  part1[4][NH_];   // partials, row1

    const int tid = threadIdx.x;
    const int cg  = tid & 127;         // column group
    const int kq  = tid >> 7;          // K quarter
    const int c0  = cg << 2;
    const int kb  = kq << 7;
    const int r0  = blockIdx.x * 2;
    const int r1  = r0 + 1;

    const float bj = bias[tid];
    float hy0 = 0.f, hy1 = 0.f, hz0 = 0.f, hz1 = 0.f;
    hys[tid] = make_float2(0.f, 0.f);
    __syncthreads();

    const float4* __restrict__ Wp  = reinterpret_cast<const float4*>(W)    + cg;
    const float4* __restrict__ WTp = reinterpret_cast<const float4*>(g_WT) + cg;
    const float* __restrict__ i2h0p = g_i2h + (size_t)r0 * T_ * NH_ + tid;
    const float* __restrict__ i2h1p = g_i2h + (size_t)r1 * T_ * NH_ + tid;
    float* __restrict__ out0 = out + (size_t)r0 * T_ * NH_ + tid;
    float* __restrict__ out1 = out + (size_t)r1 * T_ * NH_ + tid;

    for (int t = 0; t < T_; t++) {
        // ---- phase 1: a = hy @ W (this thread: 4 cols, K-quarter) ----
        float4 a0 = make_float4(0.f, 0.f, 0.f, 0.f);
        float4 a1 = make_float4(0.f, 0.f, 0.f, 0.f);
        #pragma unroll 8
        for (int i = 0; i < 128; i++) {
            const int k = kb + i;
            float4 w = Wp[(size_t)k * (NH_ / 4)];
            float2 h = hys[k];
            a0.x = fmaf(h.x, w.x, a0.x); a0.y = fmaf(h.x, w.y, a0.y);
            a0.z = fmaf(h.x, w.z, a0.z); a0.w = fmaf(h.x, w.w, a0.w);
            a1.x = fmaf(h.y, w.x, a1.x); a1.y = fmaf(h.y, w.y, a1.y);
            a1.z = fmaf(h.y, w.z, a1.z); a1.w = fmaf(h.y, w.w, a1.w);
        }
        *reinterpret_cast<float4*>(&part0[kq][c0]) = a0;
        *reinterpret_cast<float4*>(&part1[kq][c0]) = a1;
        __syncthreads();

        // reduce 4 partials for column tid, apply bias+tanh
        {
            float s0 = (part0[0][tid] + part0[1][tid]) + (part0[2][tid] + part0[3][tid]);
            float s1 = (part1[0][tid] + part1[1][tid]) + (part1[2][tid] + part1[3][tid]);
            zs[tid] = make_float2(tanhf(s0 + bj), tanhf(s1 + bj));
        }
        __syncthreads();

        // prefetch the driving input while phase-2 FMAs run
        const float i0 = i2h0p[(size_t)t * NH_];
        const float i1 = i2h1p[(size_t)t * NH_];

        // ---- phase 2: rec = z @ W^T ----
        float4 b0 = make_float4(0.f, 0.f, 0.f, 0.f);
        float4 b1 = make_float4(0.f, 0.f, 0.f, 0.f);
        #pragma unroll 8
        for (int i = 0; i < 128; i++) {
            const int k = kb + i;
            float4 w = WTp[(size_t)k * (NH_ / 4)];
            float2 z = zs[k];
            b0.x = fmaf(z.x, w.x, b0.x); b0.y = fmaf(z.x, w.y, b0.y);
            b0.z = fmaf(z.x, w.z, b0.z); b0.w = fmaf(z.x, w.w, b0.w);
            b1.x = fmaf(z.y, w.x, b1.x); b1.y = fmaf(z.y, w.y, b1.y);
            b1.z = fmaf(z.y, w.z, b1.z); b1.w = fmaf(z.y, w.w, b1.w);
        }
        *reinterpret_cast<float4*>(&part0[kq][c0]) = b0;
        *reinterpret_cast<float4*>(&part1[kq][c0]) = b1;
        __syncthreads();

        const float rr0 = (part0[0][tid] + part0[1][tid]) + (part0[2][tid] + part0[3][tid]);
        const float rr1 = (part1[0][tid] + part1[1][tid]) + (part1[2][tid] + part1[3][tid]);

        // ---- state update (GAMMA = EPSILON = 1) ----
        hz0 += DT_C * (i0 - rr0 - hy0 - hz0);
        hy0 += DT_C * hz0;
        hz1 += DT_C * (i1 - rr1 - hy1 - hz1);
        hy1 += DT_C * hz1;

        hys[tid] = make_float2(hy0, hy1);
        out0[(size_t)t * NH_] = hy0;
        out1[(size_t)t * NH_] = hy1;
        __syncthreads();
    }

    if (write_final) {  // hy_f appended after all_states
        float* fin = out + (size_t)B_ * T_ * NH_;
        fin[(size_t)r0 * NH_ + tid] = hy0;
        fin[(size_t)r1 * NH_ + tid] = hy1;
    }
}

// ---------------------------------------------------------------------------
// Launch. Inputs: x [128,1024,64] f32, x2h [64,512] f32, h2h [512,512] f32,
// bias [512] f32. Output f32: all_states [128,1024,512] (+ hy_f [128,512]).
// ---------------------------------------------------------------------------
extern "C" void kernel_launch(void* const* d_in, const int* in_sizes, int n_in,
                              void* d_out, int out_size) {
    const float* x    = (const float*)d_in[0];
    const float* x2h  = (const float*)d_in[1];
    const float* h2h  = (const float*)d_in[2];
    const float* bias = (const float*)d_in[3];
    float* out = (float*)d_out;

    const long long states_elems = (long long)B_ * T_ * NH_;
    int write_final = ((long long)out_size >= states_elems + (long long)B_ * NH_) ? 1 : 0;

    k_transpose<<<dim3(NH_ / 32, NH_ / 32), dim3(32, 8)>>>(h2h);
    k_i2h<<<dim3(NH_ / 64, (B_ * T_) / 64), 256>>>(x, x2h);
    k_scan<<<B_ / 2, NH_>>>(h2h, bias, out, write_final);
}

// round 8
// speedup vs baseline: 2.7520x; 1.2346x over previous
#include <cuda_runtime.h>
#include <cstddef>
#include <cstdint>

#define B_   128
#define T_   1024
#define NI_  64
#define NH_  512
#define DT_C 0.01f

#define S_   16    // N-slices per batch group
#define NS_  32    // hidden cols per slice
#define G_   8     // batch groups
#define MG_  16    // batch rows per group

// __device__ scratch (allocation-free rule)
__device__ float g_i2h[(size_t)B_ * T_ * NH_];     // tanh(x @ x2h), [B][T][NH]
__device__ float g_hyT[G_][NH_][MG_];              // hy exchange, transposed [k][m]
__device__ float g_zT [G_][NH_][MG_];              // z  exchange, transposed [k][m]
__device__ int   g_flagH[G_][S_];
__device__ int   g_flagZ[G_][S_];

// ---------------------------------------------------------------------------
// Reset flags (must run before each scan launch; graph replays re-run it)
// ---------------------------------------------------------------------------
__global__ void k_reset() {
    int t = blockIdx.x * blockDim.x + threadIdx.x;
    if (t < G_ * S_) {
        ((int*)g_flagH)[t] = 0;
        ((int*)g_flagZ)[t] = 0;
    }
}

// ---------------------------------------------------------------------------
// i2h = tanh(x @ x2h).  x: [B*T, 64], x2h: [64, 512].
// ---------------------------------------------------------------------------
__global__ __launch_bounds__(256) void k_i2h(const float* __restrict__ x,
                                             const float* __restrict__ x2h) {
    __shared__ float xsT[64][64];
    __shared__ float ws[64][64];
    int row0 = blockIdx.y * 64;
    int col0 = blockIdx.x * 64;
    int tid  = threadIdx.x;

    const float4* xsrc = reinterpret_cast<const float4*>(x + (size_t)row0 * NI_);
    for (int i = tid; i < 1024; i += 256) {
        float4 v = xsrc[i];
        int m = i >> 4;
        int k = (i & 15) * 4;
        xsT[k + 0][m] = v.x; xsT[k + 1][m] = v.y;
        xsT[k + 2][m] = v.z; xsT[k + 3][m] = v.w;
    }
    for (int i = tid; i < 1024; i += 256) {
        int k = i >> 4;
        int c = (i & 15) * 4;
        float4 v = *reinterpret_cast<const float4*>(x2h + (size_t)k * NH_ + col0 + c);
        *reinterpret_cast<float4*>(&ws[k][c]) = v;
    }
    __syncthreads();

    int tx = tid & 15, ty = tid >> 4;
    int m0 = ty * 4, n0 = tx * 4;
    float acc[4][4] = {};
    #pragma unroll 4
    for (int k = 0; k < 64; k++) {
        float4 a = *reinterpret_cast<float4*>(&xsT[k][m0]);
        float4 b = *reinterpret_cast<float4*>(&ws[k][n0]);
        float av[4] = {a.x, a.y, a.z, a.w};
        float bv[4] = {b.x, b.y, b.z, b.w};
        #pragma unroll
        for (int i = 0; i < 4; i++)
            #pragma unroll
            for (int j = 0; j < 4; j++)
                acc[i][j] = fmaf(av[i], bv[j], acc[i][j]);
    }
    #pragma unroll
    for (int i = 0; i < 4; i++) {
        float4 o;
        o.x = tanhf(acc[i][0]); o.y = tanhf(acc[i][1]);
        o.z = tanhf(acc[i][2]); o.w = tanhf(acc[i][3]);
        *reinterpret_cast<float4*>(&g_i2h[(size_t)(row0 + m0 + i) * NH_ + col0 + n0]) = o;
    }
}

// ---------------------------------------------------------------------------
// Persistent scan: 128 CTAs = 8 batch groups x 16 N-slices, 512 threads.
// W[:,slice] and WT[:,slice] live in SMEM for the whole run (zero L2 weight
// traffic). z / hy exchanged per step via small transposed gmem buffers with
// monotonic flag sync inside each 16-CTA group.
//
// SMEM layout (floats):
//   Ws   [512][32]      @ 0       (phase1 weights, k-major, float4-readable)
//   WTs  [512][36]      @ 16384   (phase2 weights = W rows, padded 36)
//   xbuf [512][20]      @ 34816   (exchange staging, [k][m], padded 20)
//   parts[4][16][36]    @ 45056   (K-quarter partials)
// total 47360 floats = 189440 bytes (dynamic, opt-in)
// ---------------------------------------------------------------------------
#define SMEM_BYTES 189440

__global__ __launch_bounds__(512, 1) void k_scan(const float* __restrict__ W,
                                                 const float* __restrict__ bias,
                                                 float* __restrict__ out,
                                                 int write_final) {
    extern __shared__ float sm[];
    float4* Ws4   = reinterpret_cast<float4*>(sm);        // [k*8 + ngrp]
    float*  WTs   = sm + 16384;                           // [k*36 + n]
    float*  xbuf  = sm + 34816;                           // [k*20 + m]
    float*  parts = sm + 45056;                           // [(kq*16+m)*36 + n]

    const int tid = threadIdx.x;
    const int s   = blockIdx.x & 15;   // N-slice
    const int g   = blockIdx.x >> 4;   // batch group

    // GEMV mapping: kq = K-quarter, mloc = row, ngrp = 4-col group
    const int kq   = tid >> 7;
    const int rem  = tid & 127;
    const int mloc = rem >> 3;
    const int ngrp = rem & 7;
    const int kb   = kq << 7;

    // state/update mapping: thread owns (m, n)
    const int m = tid >> 5;
    const int n = tid & 31;

    // ---- prologue: load weight slices into SMEM ----
    {
        const float4* W4 = reinterpret_cast<const float4*>(W);
        // Ws[k][n] = W[k][s*32+n]
        #pragma unroll
        for (int j = 0; j < 8; j++) {
            int f4 = tid + j * 512;          // 4096 float4
            int k  = f4 >> 3, ng = f4 & 7;
            Ws4[k * 8 + ng] = W4[(size_t)k * 128 + s * 8 + ng];
        }
        // WTs[k][r] = W[s*32+r][k]
        #pragma unroll
        for (int j = 0; j < 8; j++) {
            int f4  = tid + j * 512;         // 4096 float4 of W rows
            int r   = f4 >> 7;
            int kc4 = f4 & 127;
            float4 v = W4[(size_t)(s * 32 + r) * 128 + kc4];
            int k = kc4 * 4;
            WTs[(k + 0) * 36 + r] = v.x;
            WTs[(k + 1) * 36 + r] = v.y;
            WTs[(k + 2) * 36 + r] = v.z;
            WTs[(k + 3) * 36 + r] = v.w;
        }
    }
    const float bj = __ldg(bias + s * NS_ + n);
    float hy = 0.f, hz = 0.f;
    __syncthreads();

    const size_t io_base = ((size_t)(g * MG_ + m) * T_) * NH_ + s * NS_ + n;
    volatile int* fH = &g_flagH[g][0];
    volatile int* fZ = &g_flagZ[g][0];

    for (int t = 0; t < T_; t++) {
        // prefetch driving input early (hide DRAM latency behind the GEMVs)
        const float inp = __ldg(&g_i2h[io_base + (size_t)t * NH_]);

        if (t == 0) {
            // hy = 0  =>  z[m][k] = tanh(bias[k]) for every m; fill locally.
            for (int idx = tid; idx < NH_ * MG_; idx += 512) {
                int k = idx >> 4, mm = idx & 15;
                xbuf[k * 20 + mm] = tanhf(__ldg(bias + k));
            }
            __syncthreads();
        } else {
            // ---- wait for all hy slices of step t-1, stage into xbuf ----
            if (tid < S_) {
                while (fH[tid] < t) __nanosleep(64);
                __threadfence();
            }
            __syncthreads();
            {
                const float4* src = reinterpret_cast<const float4*>(&g_hyT[g][0][0]);
                #pragma unroll
                for (int j = 0; j < 4; j++) {
                    int f4 = tid + j * 512;       // 2048 float4
                    float4 v = __ldcg(src + f4);
                    int kg = f4 >> 2, mq = f4 & 3;
                    *reinterpret_cast<float4*>(&xbuf[kg * 20 + mq * 4]) = v;
                }
            }
            __syncthreads();

            // ---- phase 1: a = hy @ W[:, slice]  (K-quarter per thread) ----
            float4 acc = make_float4(0.f, 0.f, 0.f, 0.f);
            #pragma unroll 8
            for (int i = 0; i < 128; i++) {
                const int k = kb + i;
                float4 w = Ws4[k * 8 + ngrp];
                float  h = xbuf[k * 20 + mloc];
                acc.x = fmaf(h, w.x, acc.x); acc.y = fmaf(h, w.y, acc.y);
                acc.z = fmaf(h, w.z, acc.z); acc.w = fmaf(h, w.w, acc.w);
            }
            *reinterpret_cast<float4*>(&parts[(kq * 16 + mloc) * 36 + ngrp * 4]) = acc;
            __syncthreads();

            // reduce, tanh, publish z slice
            {
                float a = (parts[(0 * 16 + m) * 36 + n] + parts[(1 * 16 + m) * 36 + n])
                        + (parts[(2 * 16 + m) * 36 + n] + parts[(3 * 16 + m) * 36 + n]);
                float z = tanhf(a + bj);
                __stcg(&g_zT[g][s * NS_ + n][m], z);
            }
            __syncthreads();
            if (tid == 0) { __threadfence(); atomicExch(&g_flagZ[g][s], t + 1); }

            // ---- wait for all z slices, stage into xbuf ----
            if (tid < S_) {
                while (fZ[tid] < t + 1) __nanosleep(64);
                __threadfence();
            }
            __syncthreads();
            {
                const float4* src = reinterpret_cast<const float4*>(&g_zT[g][0][0]);
                #pragma unroll
                for (int j = 0; j < 4; j++) {
                    int f4 = tid + j * 512;
                    float4 v = __ldcg(src + f4);
                    int kg = f4 >> 2, mq = f4 & 3;
                    *reinterpret_cast<float4*>(&xbuf[kg * 20 + mq * 4]) = v;
                }
            }
            __syncthreads();
        }

        // ---- phase 2: rec = z @ WT[:, slice] ----
        {
            float4 acc = make_float4(0.f, 0.f, 0.f, 0.f);
            #pragma unroll 8
            for (int i = 0; i < 128; i++) {
                const int k = kb + i;
                float4 w = *reinterpret_cast<const float4*>(&WTs[k * 36 + ngrp * 4]);
                float  z = xbuf[k * 20 + mloc];
                acc.x = fmaf(z, w.x, acc.x); acc.y = fmaf(z, w.y, acc.y);
                acc.z = fmaf(z, w.z, acc.z); acc.w = fmaf(z, w.w, acc.w);
            }
            *reinterpret_cast<float4*>(&parts[(kq * 16 + mloc) * 36 + ngrp * 4]) = acc;
        }
        __syncthreads();

        // reduce + state update (GAMMA = EPSILON = 1); thread owns (m, n)
        {
            float rr = (parts[(0 * 16 + m) * 36 + n] + parts[(1 * 16 + m) * 36 + n])
                     + (parts[(2 * 16 + m) * 36 + n] + parts[(3 * 16 + m) * 36 + n]);
            hz += DT_C * (inp - rr - hy - hz);
            hy += DT_C * hz;
            out[io_base + (size_t)t * NH_] = hy;
            __stcg(&g_hyT[g][s * NS_ + n][m], hy);
        }
        __syncthreads();
        if (tid == 0) { __threadfence(); atomicExch(&g_flagH[g][s], t + 1); }
    }

    if (write_final) {
        out[(size_t)B_ * T_ * NH_ + (size_t)(g * MG_ + m) * NH_ + s * NS_ + n] = hy;
    }
}

// ---------------------------------------------------------------------------
// Launch. Inputs: x [128,1024,64] f32, x2h [64,512] f32, h2h [512,512] f32,
// bias [512] f32. Output f32: all_states [128,1024,512] (+ hy_f [128,512]).
// ---------------------------------------------------------------------------
extern "C" void kernel_launch(void* const* d_in, const int* in_sizes, int n_in,
                              void* d_out, int out_size) {
    const float* x    = (const float*)d_in[0];
    const float* x2h  = (const float*)d_in[1];
    const float* h2h  = (const float*)d_in[2];
    const float* bias = (const float*)d_in[3];
    float* out = (float*)d_out;

    const long long states_elems = (long long)B_ * T_ * NH_;
    int write_final = ((long long)out_size >= states_elems + (long long)B_ * NH_) ? 1 : 0;

    cudaFuncSetAttribute(k_scan, cudaFuncAttributeMaxDynamicSharedMemorySize, SMEM_BYTES);

    k_reset<<<1, 256>>>();
    k_i2h<<<dim3(NH_ / 64, (B_ * T_) / 64), 256>>>(x, x2h);
    k_scan<<<G_ * S_, 512, SMEM_BYTES>>>(h2h, bias, out, write_final);
}